// round 5
// baseline (speedup 1.0000x reference)
#include <cuda_runtime.h>
#include <math.h>

#define N_NODES_MAX 50000
#define E_MAX 800000
#define N_GRAPHS 512
#define HID 128

typedef unsigned long long ull;

// ---------------- scratch ----------------
__device__ float g_a[(size_t)N_NODES_MAX * HID];    // gather output
__device__ float g_h[(size_t)N_NODES_MAX * HID];    // act1
__device__ int   g_degi[N_NODES_MAX];
__device__ int   g_off[N_NODES_MAX + 1];
__device__ int   g_cur[N_NODES_MAX];
__device__ float g_dinv[N_NODES_MAX];   // 1/sqrt(deg+1)
__device__ float g_invd[N_NODES_MAX];   // 1/(deg+1)
__device__ ull   g_csr[E_MAX];          // {norm(hi32), src(lo32)} grouped by dst
__device__ int   g_bsum[64];
__device__ float g_sums[N_GRAPHS * HID];
__device__ float g_cnt[N_GRAPHS];
__device__ int   g_is64;

// ---------------- packed f32x2 helpers ----------------
__device__ __forceinline__ ull pk2(float a, float b) {
    ull r;
    asm("mov.b64 %0, {%1, %2};" : "=l"(r) : "f"(a), "f"(b));
    return r;
}
__device__ __forceinline__ float2 upk2(ull v) {
    float2 f;
    asm("mov.b64 {%0, %1}, %2;" : "=f"(f.x), "=f"(f.y) : "l"(v));
    return f;
}
__device__ __forceinline__ void ffma2(ull& d, ull a, ull b) {
    asm("fma.rn.f32x2 %0, %1, %2, %3;" : "=l"(d) : "l"(a), "l"(b), "l"(d));
}
__device__ __forceinline__ int load_idx(const void* p, long i, int is64) {
    if (is64) return (int)((const long long*)p)[i];
    return ((const int*)p)[i];
}
__device__ __forceinline__ void red_add_v4(float* addr, float4 v) {
    size_t ga = __cvta_generic_to_global(addr);
    asm volatile("red.global.add.v4.f32 [%0], {%1, %2, %3, %4};"
                 :: "l"(ga), "f"(v.x), "f"(v.y), "f"(v.z), "f"(v.w) : "memory");
}

// ---------------- degree histogram + index dtype detection ----------------
__global__ void deg_k(const void* __restrict__ ei, int E) {
    __shared__ int s64;
    if (threadIdx.x == 0) {
        const ull* e = (const ull*)ei;
        int f = 1;
#pragma unroll
        for (int i = 0; i < 16; i++)
            if (e[i] >> 32) f = 0;
        s64 = f;
        if (blockIdx.x == 0) g_is64 = f;
    }
    __syncthreads();
    int e = blockIdx.x * blockDim.x + threadIdx.x;
    if (e >= E) return;
    int d = load_idx(ei, (long)E + e, s64);
    atomicAdd(&g_degi[d], 1);
}

// ---------------- scan phase 1: per-block exclusive + block totals ----------
__global__ void scan1_k(int n) {
    __shared__ int wsum[32];
    const int tid = threadIdx.x, lane = tid & 31, w = tid >> 5;
    int i = blockIdx.x * 1024 + tid;
    int v = (i < n) ? g_degi[i] : 0;
    int x = v;
#pragma unroll
    for (int o = 1; o < 32; o <<= 1) {
        int y = __shfl_up_sync(~0u, x, o);
        if (lane >= o) x += y;
    }
    if (lane == 31) wsum[w] = x;
    __syncthreads();
    if (w == 0) {
        int s = wsum[lane];
#pragma unroll
        for (int o = 1; o < 32; o <<= 1) {
            int y = __shfl_up_sync(~0u, s, o);
            if (lane >= o) s += y;
        }
        wsum[lane] = s;
    }
    __syncthreads();
    int pre = (w > 0) ? wsum[w - 1] : 0;
    if (i < n) g_off[i] = pre + x - v;
    if (tid == 1023) g_bsum[blockIdx.x] = pre + x;
}

// ---------------- scan phase 2 (block prefix recomputed per block) + fixup --
__global__ void scan3_k(int n, int nblk) {
    __shared__ int incl[64];
    const int tid = threadIdx.x, lane = tid & 31;
    if (tid < 64) {
        int v = (tid < nblk) ? g_bsum[tid] : 0;
        int x = v;
#pragma unroll
        for (int o = 1; o < 32; o <<= 1) {
            int y = __shfl_up_sync(~0u, x, o);
            if (lane >= o) x += y;
        }
        incl[tid] = x;  // per-warp inclusive
    }
    __syncthreads();
    if (tid >= 32 && tid < 64) incl[tid] += incl[31];  // add warp0 total
    __syncthreads();
    if (blockIdx.x == 0 && tid == 63) g_off[n] = incl[63];
    int i = blockIdx.x * blockDim.x + tid;
    if (i >= n) return;
    int blk = i >> 10;
    int bpre = (blk > 0) ? incl[blk - 1] : 0;
    int off = g_off[i] + bpre;
    g_off[i] = off;
    g_cur[i] = off;
    float dg = (float)g_degi[i] + 1.0f;
    g_dinv[i] = rsqrtf(dg);
    g_invd[i] = 1.0f / dg;
}

// ---------------- CSR fill: {norm, src} grouped by dst ----------------
__global__ void fill_k(const void* __restrict__ ei, int E) {
    int e = blockIdx.x * blockDim.x + threadIdx.x;
    if (e >= E) return;
    int is64 = g_is64;
    int s = load_idx(ei, e, is64);
    int d = load_idx(ei, (long)E + e, is64);
    float norm = g_dinv[s] * g_dinv[d];
    int pos = atomicAdd(&g_cur[d], 1);
    g_csr[pos] = ((ull)__float_as_uint(norm) << 32) | (unsigned)s;
}

// ---------------- gather-reduce: warp per dst node, 4-edge ILP -------------
template <int CH>
__global__ void gather_k(const float* __restrict__ feat, float* __restrict__ out,
                         int start, int end) {
    int node = start + blockIdx.x * (blockDim.x >> 5) + (threadIdx.x >> 5);
    if (node >= end) return;
    const int lane = threadIdx.x & 31;
    int p = g_off[node], pend = g_off[node + 1];

    if (CH == 128) {
        const float4* f4 = (const float4*)feat;
        float4 acc = make_float4(0.f, 0.f, 0.f, 0.f);
        for (; p + 4 <= pend; p += 4) {
            ull e0 = __ldg(&g_csr[p]),     e1 = __ldg(&g_csr[p + 1]);
            ull e2 = __ldg(&g_csr[p + 2]), e3 = __ldg(&g_csr[p + 3]);
            int s0 = (int)(unsigned)e0; float n0 = __uint_as_float((unsigned)(e0 >> 32));
            int s1 = (int)(unsigned)e1; float n1 = __uint_as_float((unsigned)(e1 >> 32));
            int s2 = (int)(unsigned)e2; float n2 = __uint_as_float((unsigned)(e2 >> 32));
            int s3 = (int)(unsigned)e3; float n3 = __uint_as_float((unsigned)(e3 >> 32));
            float4 v0 = __ldg(&f4[(long)s0 * 32 + lane]);
            float4 v1 = __ldg(&f4[(long)s1 * 32 + lane]);
            float4 v2 = __ldg(&f4[(long)s2 * 32 + lane]);
            float4 v3 = __ldg(&f4[(long)s3 * 32 + lane]);
            acc.x = fmaf(v0.x, n0, acc.x); acc.y = fmaf(v0.y, n0, acc.y);
            acc.z = fmaf(v0.z, n0, acc.z); acc.w = fmaf(v0.w, n0, acc.w);
            acc.x = fmaf(v1.x, n1, acc.x); acc.y = fmaf(v1.y, n1, acc.y);
            acc.z = fmaf(v1.z, n1, acc.z); acc.w = fmaf(v1.w, n1, acc.w);
            acc.x = fmaf(v2.x, n2, acc.x); acc.y = fmaf(v2.y, n2, acc.y);
            acc.z = fmaf(v2.z, n2, acc.z); acc.w = fmaf(v2.w, n2, acc.w);
            acc.x = fmaf(v3.x, n3, acc.x); acc.y = fmaf(v3.y, n3, acc.y);
            acc.z = fmaf(v3.z, n3, acc.z); acc.w = fmaf(v3.w, n3, acc.w);
        }
        for (; p < pend; p++) {
            ull e0 = __ldg(&g_csr[p]);
            int s0 = (int)(unsigned)e0; float n0 = __uint_as_float((unsigned)(e0 >> 32));
            float4 v0 = __ldg(&f4[(long)s0 * 32 + lane]);
            acc.x = fmaf(v0.x, n0, acc.x); acc.y = fmaf(v0.y, n0, acc.y);
            acc.z = fmaf(v0.z, n0, acc.z); acc.w = fmaf(v0.w, n0, acc.w);
        }
        float id = g_invd[node];
        float4 sv = __ldg(&f4[(long)node * 32 + lane]);
        acc.x = fmaf(sv.x, id, acc.x); acc.y = fmaf(sv.y, id, acc.y);
        acc.z = fmaf(sv.z, id, acc.z); acc.w = fmaf(sv.w, id, acc.w);
        ((float4*)out)[(long)node * 32 + lane] = acc;
    } else {  // CH == 96
        float a0 = 0.f, a1 = 0.f, a2 = 0.f;
        for (; p + 4 <= pend; p += 4) {
            ull e0 = __ldg(&g_csr[p]),     e1 = __ldg(&g_csr[p + 1]);
            ull e2 = __ldg(&g_csr[p + 2]), e3 = __ldg(&g_csr[p + 3]);
            int s0 = (int)(unsigned)e0; float n0 = __uint_as_float((unsigned)(e0 >> 32));
            int s1 = (int)(unsigned)e1; float n1 = __uint_as_float((unsigned)(e1 >> 32));
            int s2 = (int)(unsigned)e2; float n2 = __uint_as_float((unsigned)(e2 >> 32));
            int s3 = (int)(unsigned)e3; float n3 = __uint_as_float((unsigned)(e3 >> 32));
            const float* r0 = feat + (long)s0 * 96 + lane;
            const float* r1 = feat + (long)s1 * 96 + lane;
            const float* r2 = feat + (long)s2 * 96 + lane;
            const float* r3 = feat + (long)s3 * 96 + lane;
            float u00 = __ldg(r0), u01 = __ldg(r0 + 32), u02 = __ldg(r0 + 64);
            float u10 = __ldg(r1), u11 = __ldg(r1 + 32), u12 = __ldg(r1 + 64);
            float u20 = __ldg(r2), u21 = __ldg(r2 + 32), u22 = __ldg(r2 + 64);
            float u30 = __ldg(r3), u31 = __ldg(r3 + 32), u32 = __ldg(r3 + 64);
            a0 = fmaf(u00, n0, a0); a1 = fmaf(u01, n0, a1); a2 = fmaf(u02, n0, a2);
            a0 = fmaf(u10, n1, a0); a1 = fmaf(u11, n1, a1); a2 = fmaf(u12, n1, a2);
            a0 = fmaf(u20, n2, a0); a1 = fmaf(u21, n2, a1); a2 = fmaf(u22, n2, a2);
            a0 = fmaf(u30, n3, a0); a1 = fmaf(u31, n3, a1); a2 = fmaf(u32, n3, a2);
        }
        for (; p < pend; p++) {
            ull e0 = __ldg(&g_csr[p]);
            int s0 = (int)(unsigned)e0; float n0 = __uint_as_float((unsigned)(e0 >> 32));
            const float* r0 = feat + (long)s0 * 96 + lane;
            a0 = fmaf(__ldg(r0), n0, a0);
            a1 = fmaf(__ldg(r0 + 32), n0, a1);
            a2 = fmaf(__ldg(r0 + 64), n0, a2);
        }
        float id = g_invd[node];
        const float* sv = feat + (long)node * 96 + lane;
        a0 = fmaf(__ldg(sv), id, a0);
        a1 = fmaf(__ldg(sv + 32), id, a1);
        a2 = fmaf(__ldg(sv + 64), id, a2);
        float* o = out + (long)node * 96 + lane;
        o[0] = a0; o[32] = a1; o[64] = a2;
    }
}

// ------- dense transform + epilogue: relu(X @ W + b); POOL reduces to g_sums -
template <int KIN, bool POOL>
__global__ void gemm_k(const float* __restrict__ X, const float* __restrict__ W,
                       const float* __restrict__ bias, float* __restrict__ out,
                       const void* __restrict__ batch, int row0, int rowend) {
    __shared__ ulonglong2 Ws2[32 * 32];
    __shared__ ull Xs2[64 * 32];
    const int tid  = threadIdx.x;
    const int lane = tid & 31;
    const int warp = tid >> 5;
    const int rbase = row0 + blockIdx.x * 64;

    ull acc[8][2];
#pragma unroll
    for (int r = 0; r < 8; r++) { acc[r][0] = 0ull; acc[r][1] = 0ull; }

    const int KT = KIN / 32;
    for (int kt = 0; kt < KT; kt++) {
#pragma unroll
        for (int j = 0; j < 4; j++) {
            int f = tid + j * 256;
            float4 w = __ldg(&((const float4*)W)[kt * 1024 + f]);
            Ws2[f] = make_ulonglong2(pk2(w.x, w.y), pk2(w.z, w.w));
        }
#pragma unroll
        for (int j = 0; j < 2; j++) {
            int f = tid + j * 256;
            int row = f >> 3;
            int kq = f & 7;
            int gr = rbase + row;
            float4 v = make_float4(0.f, 0.f, 0.f, 0.f);
            if (gr < rowend)
                v = *(const float4*)(X + (long)gr * KIN + kt * 32 + kq * 4);
            int bb = row * 32 + kq * 4;
            Xs2[bb + 0] = pk2(v.x, v.x);
            Xs2[bb + 1] = pk2(v.y, v.y);
            Xs2[bb + 2] = pk2(v.z, v.z);
            Xs2[bb + 3] = pk2(v.w, v.w);
        }
        __syncthreads();
#pragma unroll
        for (int k = 0; k < 32; k++) {
            ulonglong2 w = Ws2[k * 32 + lane];
#pragma unroll
            for (int r = 0; r < 8; r++) {
                ull xx = Xs2[(warp * 8 + r) * 32 + k];
                ffma2(acc[r][0], xx, w.x);
                ffma2(acc[r][1], xx, w.y);
            }
        }
        __syncthreads();
    }
    float4 bb = __ldg(&((const float4*)bias)[lane]);
    int is64 = POOL ? g_is64 : 0;
#pragma unroll
    for (int r = 0; r < 8; r++) {
        int row = rbase + warp * 8 + r;
        if (row < rowend) {
            float2 a = upk2(acc[r][0]);
            float2 b = upk2(acc[r][1]);
            float4 o;
            o.x = fmaxf(a.x + bb.x, 0.f);
            o.y = fmaxf(a.y + bb.y, 0.f);
            o.z = fmaxf(b.x + bb.z, 0.f);
            o.w = fmaxf(b.y + bb.w, 0.f);
            if (!POOL) {
                *(float4*)(out + (long)row * HID + lane * 4) = o;
            } else {
                int g = load_idx(batch, row, is64);
                red_add_v4(g_sums + (long)g * HID + lane * 4, o);
                if (lane == 0) atomicAdd(&g_cnt[g], 1.0f);
            }
        }
    }
}

// ---------------- mean + final linear ----------------
__global__ void final_k(const float* __restrict__ Wlin, const float* __restrict__ blin,
                        float* __restrict__ out) {
    int g = blockIdx.x;
    int t = threadIdx.x;  // 128
    float c = fmaxf(g_cnt[g], 1.0f);
    float s = g_sums[g * HID + t] / c;
    float p0 = s * Wlin[2 * t];
    float p1 = s * Wlin[2 * t + 1];
#pragma unroll
    for (int off = 16; off; off >>= 1) {
        p0 += __shfl_down_sync(0xffffffffu, p0, off);
        p1 += __shfl_down_sync(0xffffffffu, p1, off);
    }
    __shared__ float s0[4], s1[4];
    int w = t >> 5;
    if ((t & 31) == 0) { s0[w] = p0; s1[w] = p1; }
    __syncthreads();
    if (t == 0) {
        out[g * 2 + 0] = s0[0] + s0[1] + s0[2] + s0[3] + blin[0];
        out[g * 2 + 1] = s1[0] + s1[1] + s1[2] + s1[3] + blin[1];
    }
}

// ---------------- launcher ----------------
#define NCHUNK 4

extern "C" void kernel_launch(void* const* d_in, const int* in_sizes, int n_in,
                              void* d_out, int out_size) {
    (void)out_size;
    const float* x     = (const float*)d_in[0];
    const void*  ei    = d_in[1];
    const void*  batch = d_in[2];
    int base = (n_in >= 10) ? 4 : 3;
    const float* W1   = (const float*)d_in[base + 0];
    const float* b1   = (const float*)d_in[base + 1];
    const float* W2   = (const float*)d_in[base + 2];
    const float* b2   = (const float*)d_in[base + 3];
    const float* Wlin = (const float*)d_in[base + 4];
    const float* blin = (const float*)d_in[base + 5];

    const int N = in_sizes[0] / 96;
    const int E = in_sizes[1] / 2;
    const int NBLK = (N + 1023) >> 10;  // <= 64
    float* out = (float*)d_out;

    // resource init (host objects only; identical work every call)
    static cudaStream_t s1 = 0;
    static cudaEvent_t evA[NCHUNK], evB[NCHUNK], evJ1, evJ2;
    if (!s1) {
        cudaStreamCreateWithFlags(&s1, cudaStreamNonBlocking);
        for (int i = 0; i < NCHUNK; i++) {
            cudaEventCreateWithFlags(&evA[i], cudaEventDisableTiming);
            cudaEventCreateWithFlags(&evB[i], cudaEventDisableTiming);
        }
        cudaEventCreateWithFlags(&evJ1, cudaEventDisableTiming);
        cudaEventCreateWithFlags(&evJ2, cudaEventDisableTiming);
    }

    // chunk boundaries aligned to 64-row gemm tiles
    int cb[NCHUNK + 1];
    int step = (((N + NCHUNK - 1) / NCHUNK + 63) / 64) * 64;
    for (int i = 0; i <= NCHUNK; i++) {
        int v = i * step;
        cb[i] = v < N ? v : N;
    }

    void *p_degi, *p_sums, *p_cnt, *p_a, *p_h;
    cudaGetSymbolAddress(&p_degi, g_degi);
    cudaGetSymbolAddress(&p_sums, g_sums);
    cudaGetSymbolAddress(&p_cnt, g_cnt);
    cudaGetSymbolAddress(&p_a, g_a);
    cudaGetSymbolAddress(&p_h, g_h);

    cudaMemsetAsync(p_degi, 0, (size_t)N * sizeof(int), 0);
    cudaMemsetAsync(p_sums, 0, (size_t)N_GRAPHS * HID * sizeof(float), 0);
    cudaMemsetAsync(p_cnt, 0, (size_t)N_GRAPHS * sizeof(float), 0);

    // prep chain (stream 0)
    deg_k<<<(E + 255) / 256, 256>>>(ei, E);
    scan1_k<<<NBLK, 1024>>>(N);
    scan3_k<<<(N + 255) / 256, 256>>>(N, NBLK);
    fill_k<<<(E + 255) / 256, 256>>>(ei, E);

    // ---- layer 1: gather96 chunks (s0) pipelined with gemm96 chunks (s1) ----
    for (int c = 0; c < NCHUNK; c++) {
        int st = cb[c], en = cb[c + 1];
        if (st >= en) { cudaEventRecord(evA[c], 0); continue; }
        int nw = en - st;
        gather_k<96><<<(nw + 15) / 16, 512>>>(x, (float*)p_a, st, en);
        cudaEventRecord(evA[c], 0);
    }
    for (int c = 0; c < NCHUNK; c++) {
        int st = cb[c], en = cb[c + 1];
        cudaStreamWaitEvent(s1, evA[c], 0);
        if (st >= en) continue;
        gemm_k<96, false><<<(en - st + 63) / 64, 256, 0, s1>>>(
            (const float*)p_a, W1, b1, (float*)p_h, nullptr, st, en);
    }
    cudaEventRecord(evJ1, s1);
    cudaStreamWaitEvent(0, evJ1, 0);

    // ---- layer 2: gather128 chunks (s0) pipelined with gemm128+pool (s1) ----
    for (int c = 0; c < NCHUNK; c++) {
        int st = cb[c], en = cb[c + 1];
        if (st >= en) { cudaEventRecord(evB[c], 0); continue; }
        int nw = en - st;
        gather_k<128><<<(nw + 15) / 16, 512>>>((const float*)p_h, (float*)p_a, st, en);
        cudaEventRecord(evB[c], 0);
    }
    for (int c = 0; c < NCHUNK; c++) {
        int st = cb[c], en = cb[c + 1];
        cudaStreamWaitEvent(s1, evB[c], 0);
        if (st >= en) continue;
        gemm_k<128, true><<<(en - st + 63) / 64, 256, 0, s1>>>(
            (const float*)p_a, W2, b2, nullptr, batch, st, en);
    }
    cudaEventRecord(evJ2, s1);
    cudaStreamWaitEvent(0, evJ2, 0);

    final_k<<<N_GRAPHS, HID>>>(Wlin, blin, out);
}

// round 6
// speedup vs baseline: 1.3831x; 1.3831x over previous
#include <cuda_runtime.h>
#include <math.h>

#define N_NODES_MAX 50000
#define E_MAX 800000
#define N_GRAPHS 512
#define HID 128

typedef unsigned long long ull;

// ---------------- scratch ----------------
__device__ float g_h[(size_t)N_NODES_MAX * HID];    // xW1, later gatherL2 out
__device__ float g_a[(size_t)N_NODES_MAX * HID];    // act1
__device__ int   g_degi[N_NODES_MAX];
__device__ int   g_off[N_NODES_MAX + 1];
__device__ int   g_cur[N_NODES_MAX];
__device__ float g_dinv[N_NODES_MAX];   // 1/sqrt(deg+1)
__device__ float g_invd[N_NODES_MAX];   // 1/(deg+1)
__device__ int   g_csr[E_MAX];          // src ids grouped by dst
__device__ int   g_bsum[64];
__device__ float g_sums[N_GRAPHS * HID];
__device__ float g_cnt[N_GRAPHS];
__device__ int   g_is64;

// ---------------- packed f32x2 helpers ----------------
__device__ __forceinline__ ull pk2(float a, float b) {
    ull r;
    asm("mov.b64 %0, {%1, %2};" : "=l"(r) : "f"(a), "f"(b));
    return r;
}
__device__ __forceinline__ float2 upk2(ull v) {
    float2 f;
    asm("mov.b64 {%0, %1}, %2;" : "=f"(f.x), "=f"(f.y) : "l"(v));
    return f;
}
__device__ __forceinline__ void ffma2(ull& d, ull a, ull b) {
    asm("fma.rn.f32x2 %0, %1, %2, %3;" : "=l"(d) : "l"(a), "l"(b), "l"(d));
}
__device__ __forceinline__ int load_idx(const void* p, long i, int is64) {
    if (is64) return (int)((const long long*)p)[i];
    return ((const int*)p)[i];
}
__device__ __forceinline__ void red_add_v4(float* addr, float4 v) {
    size_t ga = __cvta_generic_to_global(addr);
    asm volatile("red.global.add.v4.f32 [%0], {%1, %2, %3, %4};"
                 :: "l"(ga), "f"(v.x), "f"(v.y), "f"(v.z), "f"(v.w) : "memory");
}

// ------- degree histogram (4 edges/thread for atomic MLP) + dtype detect ----
__global__ void deg_k(const void* __restrict__ ei, int E) {
    __shared__ int s64;
    if (threadIdx.x == 0) {
        const ull* e = (const ull*)ei;
        int f = 1;
#pragma unroll
        for (int i = 0; i < 16; i++)
            if (e[i] >> 32) f = 0;
        s64 = f;
        if (blockIdx.x == 0) g_is64 = f;
    }
    __syncthreads();
    int is64 = s64;
    long base = ((long)blockIdx.x * blockDim.x + threadIdx.x) * 4;
#pragma unroll
    for (int j = 0; j < 4; j++) {
        long e = base + j;
        if (e < E) {
            int d = load_idx(ei, (long)E + e, is64);
            atomicAdd(&g_degi[d], 1);
        }
    }
}

// ---------------- scan phase 1: per-block exclusive + block totals ----------
__global__ void scan1_k(int n) {
    __shared__ int wsum[32];
    const int tid = threadIdx.x, lane = tid & 31, w = tid >> 5;
    int i = blockIdx.x * 1024 + tid;
    int v = (i < n) ? g_degi[i] : 0;
    int x = v;
#pragma unroll
    for (int o = 1; o < 32; o <<= 1) {
        int y = __shfl_up_sync(~0u, x, o);
        if (lane >= o) x += y;
    }
    if (lane == 31) wsum[w] = x;
    __syncthreads();
    if (w == 0) {
        int s = wsum[lane];
#pragma unroll
        for (int o = 1; o < 32; o <<= 1) {
            int y = __shfl_up_sync(~0u, s, o);
            if (lane >= o) s += y;
        }
        wsum[lane] = s;
    }
    __syncthreads();
    int pre = (w > 0) ? wsum[w - 1] : 0;
    if (i < n) g_off[i] = pre + x - v;
    if (tid == 1023) g_bsum[blockIdx.x] = pre + x;
}

// ---------------- scan phase 2 (block prefix recomputed per block) + fixup --
__global__ void scan3_k(int n, int nblk) {
    __shared__ int incl[64];
    const int tid = threadIdx.x, lane = tid & 31;
    if (tid < 64) {
        int v = (tid < nblk) ? g_bsum[tid] : 0;
        int x = v;
#pragma unroll
        for (int o = 1; o < 32; o <<= 1) {
            int y = __shfl_up_sync(~0u, x, o);
            if (lane >= o) x += y;
        }
        incl[tid] = x;
    }
    __syncthreads();
    if (tid >= 32 && tid < 64) incl[tid] += incl[31];
    __syncthreads();
    if (blockIdx.x == 0 && tid == 63) g_off[n] = incl[63];
    int i = blockIdx.x * blockDim.x + tid;
    if (i >= n) return;
    int blk = i >> 10;
    int bpre = (blk > 0) ? incl[blk - 1] : 0;
    int off = g_off[i] + bpre;
    g_off[i] = off;
    g_cur[i] = off;
    float dg = (float)g_degi[i] + 1.0f;
    g_dinv[i] = rsqrtf(dg);
    g_invd[i] = 1.0f / dg;
}

// ---------- CSR fill: src only, 4 edges/thread for atomic MLP ----------
__global__ void fill_k(const void* __restrict__ ei, int E) {
    int is64 = g_is64;
    long base = ((long)blockIdx.x * blockDim.x + threadIdx.x) * 4;
#pragma unroll
    for (int j = 0; j < 4; j++) {
        long e = base + j;
        if (e < E) {
            int s = load_idx(ei, e, is64);
            int d = load_idx(ei, (long)E + e, is64);
            int pos = atomicAdd(&g_cur[d], 1);
            g_csr[pos] = s;
        }
    }
}

// ------ gather-reduce over 128 cols: warp per dst node, 4-edge ILP ---------
// out[node] = sum_e dinv[node]*dinv[src]*feat[src] + invd[node]*feat[node]
// EPI: additionally + bias then relu.
template <bool EPI>
__global__ void gather128_k(const float* __restrict__ feat,
                            const float* __restrict__ bias,
                            float* __restrict__ out, int n) {
    int node = blockIdx.x * (blockDim.x >> 5) + (threadIdx.x >> 5);
    if (node >= n) return;
    const int lane = threadIdx.x & 31;
    int p = g_off[node], pend = g_off[node + 1];
    const float4* f4 = (const float4*)feat;
    float dd = g_dinv[node];

    float4 acc = make_float4(0.f, 0.f, 0.f, 0.f);
    for (; p + 4 <= pend; p += 4) {
        int s0 = __ldg(&g_csr[p]),     s1 = __ldg(&g_csr[p + 1]);
        int s2 = __ldg(&g_csr[p + 2]), s3 = __ldg(&g_csr[p + 3]);
        float n0 = dd * __ldg(&g_dinv[s0]);
        float n1 = dd * __ldg(&g_dinv[s1]);
        float n2 = dd * __ldg(&g_dinv[s2]);
        float n3 = dd * __ldg(&g_dinv[s3]);
        float4 v0 = __ldg(&f4[(long)s0 * 32 + lane]);
        float4 v1 = __ldg(&f4[(long)s1 * 32 + lane]);
        float4 v2 = __ldg(&f4[(long)s2 * 32 + lane]);
        float4 v3 = __ldg(&f4[(long)s3 * 32 + lane]);
        acc.x = fmaf(v0.x, n0, acc.x); acc.y = fmaf(v0.y, n0, acc.y);
        acc.z = fmaf(v0.z, n0, acc.z); acc.w = fmaf(v0.w, n0, acc.w);
        acc.x = fmaf(v1.x, n1, acc.x); acc.y = fmaf(v1.y, n1, acc.y);
        acc.z = fmaf(v1.z, n1, acc.z); acc.w = fmaf(v1.w, n1, acc.w);
        acc.x = fmaf(v2.x, n2, acc.x); acc.y = fmaf(v2.y, n2, acc.y);
        acc.z = fmaf(v2.z, n2, acc.z); acc.w = fmaf(v2.w, n2, acc.w);
        acc.x = fmaf(v3.x, n3, acc.x); acc.y = fmaf(v3.y, n3, acc.y);
        acc.z = fmaf(v3.z, n3, acc.z); acc.w = fmaf(v3.w, n3, acc.w);
    }
    for (; p < pend; p++) {
        int s0 = __ldg(&g_csr[p]);
        float n0 = dd * __ldg(&g_dinv[s0]);
        float4 v0 = __ldg(&f4[(long)s0 * 32 + lane]);
        acc.x = fmaf(v0.x, n0, acc.x); acc.y = fmaf(v0.y, n0, acc.y);
        acc.z = fmaf(v0.z, n0, acc.z); acc.w = fmaf(v0.w, n0, acc.w);
    }
    float id = g_invd[node];
    float4 sv = __ldg(&f4[(long)node * 32 + lane]);
    acc.x = fmaf(sv.x, id, acc.x); acc.y = fmaf(sv.y, id, acc.y);
    acc.z = fmaf(sv.z, id, acc.z); acc.w = fmaf(sv.w, id, acc.w);
    if (EPI) {
        float4 bb = __ldg(&((const float4*)bias)[lane]);
        acc.x = fmaxf(acc.x + bb.x, 0.f);
        acc.y = fmaxf(acc.y + bb.y, 0.f);
        acc.z = fmaxf(acc.z + bb.z, 0.f);
        acc.w = fmaxf(acc.w + bb.w, 0.f);
    }
    ((float4*)out)[(long)node * 32 + lane] = acc;
}

// ------- dense transform: [rows,KIN] @ [KIN,128] ------------------------
// EPI_MODE 0: plain store. 2: bias+relu+pool-reduce into g_sums/g_cnt.
template <int KIN, int EPI_MODE>
__global__ void gemm_k(const float* __restrict__ X, const float* __restrict__ W,
                       const float* __restrict__ bias, float* __restrict__ out,
                       const void* __restrict__ batch, int n) {
    __shared__ ulonglong2 Ws2[32 * 32];
    __shared__ ull Xs2[64 * 32];
    const int tid  = threadIdx.x;
    const int lane = tid & 31;
    const int warp = tid >> 5;
    const int rbase = blockIdx.x * 64;

    ull acc[8][2];
#pragma unroll
    for (int r = 0; r < 8; r++) { acc[r][0] = 0ull; acc[r][1] = 0ull; }

    const int KT = KIN / 32;
    for (int kt = 0; kt < KT; kt++) {
#pragma unroll
        for (int j = 0; j < 4; j++) {
            int f = tid + j * 256;
            float4 w = __ldg(&((const float4*)W)[kt * 1024 + f]);
            Ws2[f] = make_ulonglong2(pk2(w.x, w.y), pk2(w.z, w.w));
        }
#pragma unroll
        for (int j = 0; j < 2; j++) {
            int f = tid + j * 256;
            int row = f >> 3;
            int kq = f & 7;
            int gr = rbase + row;
            float4 v = make_float4(0.f, 0.f, 0.f, 0.f);
            if (gr < n)
                v = *(const float4*)(X + (long)gr * KIN + kt * 32 + kq * 4);
            int bb = row * 32 + kq * 4;
            Xs2[bb + 0] = pk2(v.x, v.x);
            Xs2[bb + 1] = pk2(v.y, v.y);
            Xs2[bb + 2] = pk2(v.z, v.z);
            Xs2[bb + 3] = pk2(v.w, v.w);
        }
        __syncthreads();
#pragma unroll
        for (int k = 0; k < 32; k++) {
            ulonglong2 w = Ws2[k * 32 + lane];
#pragma unroll
            for (int r = 0; r < 8; r++) {
                ull xx = Xs2[(warp * 8 + r) * 32 + k];
                ffma2(acc[r][0], xx, w.x);
                ffma2(acc[r][1], xx, w.y);
            }
        }
        __syncthreads();
    }
    float4 bb = make_float4(0.f, 0.f, 0.f, 0.f);
    if (EPI_MODE == 2) bb = __ldg(&((const float4*)bias)[lane]);
    int is64 = (EPI_MODE == 2) ? g_is64 : 0;
#pragma unroll
    for (int r = 0; r < 8; r++) {
        int row = rbase + warp * 8 + r;
        if (row < n) {
            float2 a = upk2(acc[r][0]);
            float2 b = upk2(acc[r][1]);
            if (EPI_MODE == 0) {
                *(float4*)(out + (long)row * HID + lane * 4) =
                    make_float4(a.x, a.y, b.x, b.y);
            } else {
                float4 o;
                o.x = fmaxf(a.x + bb.x, 0.f);
                o.y = fmaxf(a.y + bb.y, 0.f);
                o.z = fmaxf(b.x + bb.z, 0.f);
                o.w = fmaxf(b.y + bb.w, 0.f);
                int g = load_idx(batch, row, is64);
                red_add_v4(g_sums + (long)g * HID + lane * 4, o);
                if (lane == 0) atomicAdd(&g_cnt[g], 1.0f);
            }
        }
    }
}

// ---------------- mean + final linear ----------------
__global__ void final_k(const float* __restrict__ Wlin, const float* __restrict__ blin,
                        float* __restrict__ out) {
    int g = blockIdx.x;
    int t = threadIdx.x;  // 128
    float c = fmaxf(g_cnt[g], 1.0f);
    float s = g_sums[g * HID + t] / c;
    float p0 = s * Wlin[2 * t];
    float p1 = s * Wlin[2 * t + 1];
#pragma unroll
    for (int off = 16; off; off >>= 1) {
        p0 += __shfl_down_sync(0xffffffffu, p0, off);
        p1 += __shfl_down_sync(0xffffffffu, p1, off);
    }
    __shared__ float s0[4], s1[4];
    int w = t >> 5;
    if ((t & 31) == 0) { s0[w] = p0; s1[w] = p1; }
    __syncthreads();
    if (t == 0) {
        out[g * 2 + 0] = s0[0] + s0[1] + s0[2] + s0[3] + blin[0];
        out[g * 2 + 1] = s1[0] + s1[1] + s1[2] + s1[3] + blin[1];
    }
}

// ---------------- launcher ----------------
extern "C" void kernel_launch(void* const* d_in, const int* in_sizes, int n_in,
                              void* d_out, int out_size) {
    (void)out_size;
    const float* x     = (const float*)d_in[0];
    const void*  ei    = d_in[1];
    const void*  batch = d_in[2];
    int base = (n_in >= 10) ? 4 : 3;
    const float* W1   = (const float*)d_in[base + 0];
    const float* b1   = (const float*)d_in[base + 1];
    const float* W2   = (const float*)d_in[base + 2];
    const float* b2   = (const float*)d_in[base + 3];
    const float* Wlin = (const float*)d_in[base + 4];
    const float* blin = (const float*)d_in[base + 5];

    const int N = in_sizes[0] / 96;
    const int E = in_sizes[1] / 2;
    const int NBLK = (N + 1023) >> 10;  // <= 64
    float* out = (float*)d_out;

    static cudaStream_t s1 = 0;
    static cudaEvent_t evF, evJ;
    if (!s1) {
        cudaStreamCreateWithFlags(&s1, cudaStreamNonBlocking);
        cudaEventCreateWithFlags(&evF, cudaEventDisableTiming);
        cudaEventCreateWithFlags(&evJ, cudaEventDisableTiming);
    }

    void *p_degi, *p_sums, *p_cnt, *p_a, *p_h;
    cudaGetSymbolAddress(&p_degi, g_degi);
    cudaGetSymbolAddress(&p_sums, g_sums);
    cudaGetSymbolAddress(&p_cnt, g_cnt);
    cudaGetSymbolAddress(&p_a, g_a);
    cudaGetSymbolAddress(&p_h, g_h);

    // fork: h1 = x @ W1 on s1 (needs only x, W1 — independent of prep)
    cudaEventRecord(evF, 0);
    cudaStreamWaitEvent(s1, evF, 0);
    gemm_k<96, 0><<<(N + 63) / 64, 256, 0, s1>>>(x, W1, nullptr,
                                                 (float*)p_h, nullptr, N);
    cudaEventRecord(evJ, s1);

    // prep chain on stream 0
    cudaMemsetAsync(p_degi, 0, (size_t)N * sizeof(int), 0);
    cudaMemsetAsync(p_sums, 0, (size_t)N_GRAPHS * HID * sizeof(float), 0);
    cudaMemsetAsync(p_cnt, 0, (size_t)N_GRAPHS * sizeof(float), 0);
    deg_k<<<(E + 1023) / 1024, 256>>>(ei, E);
    scan1_k<<<NBLK, 1024>>>(N);
    scan3_k<<<(N + 255) / 256, 256>>>(N, NBLK);
    fill_k<<<(E + 1023) / 1024, 256>>>(ei, E);

    // join, then layer 1 aggregate (fused self-loop + b1 + relu)
    cudaStreamWaitEvent(0, evJ, 0);
    gather128_k<true><<<(N + 15) / 16, 512>>>((const float*)p_h, b1,
                                              (float*)p_a, N);
    // layer 2: aggregate act1, then transform + bias + relu + pool
    gather128_k<false><<<(N + 15) / 16, 512>>>((const float*)p_a, nullptr,
                                               (float*)p_h, N);
    gemm_k<128, 2><<<(N + 63) / 64, 256>>>((const float*)p_h, W2, b2,
                                           nullptr, batch, N);

    final_k<<<N_GRAPHS, HID>>>(Wlin, blin, out);
}